// round 1
// baseline (speedup 1.0000x reference)
#include <cuda_runtime.h>

// Shifted-window attention (Swin block), fully fused.
// Static shapes: B=16, H=W=56, C=384, heads=12, hd=32, window 7x7 (N=49),
// shift (3,3). 56 % 7 == 0 -> no padding; shifted path active.
// One CTA per window: 16*64 = 1024 CTAs, 256 threads each.
//
// Smem plan (floats, padded strides to avoid bank conflicts):
//   xw     [49][384]   window tokens (gathered with roll(-3,-3))
//   outbuf [49][384]   per-token concat of head outputs
//   qkvh   [49][97]    Q(0..31 scaled) | K(32..63) | V(64..95), pad to 97
//   attnS  [49*49]     logits -> softmax probs
//   wtile  [32][97]    staged weight tile (96 cols used, pad 97)
//   biasS  [12][172]   rel-pos bias, transposed per-head rows (169 used)
//   regS   [64] int    shifted-window mask region id per token
//   oidxS  [64] int    output base index per token (roll-back applied)

#define NTOK 49
#define CDIM 384
#define NHEADS 12

__global__ void __launch_bounds__(256, 1)
swin_fused_kernel(const float* __restrict__ x,
                  const float* __restrict__ qkvw,
                  const float* __restrict__ qkvb,
                  const float* __restrict__ projw,
                  const float* __restrict__ projb,
                  const float* __restrict__ table,
                  float* __restrict__ out)
{
    extern __shared__ float sm[];
    float* xw     = sm;                  // 18816
    float* outbuf = xw + 18816;          // 18816
    float* qkvh   = outbuf + 18816;      // 4753  (49*97)
    float* attnS  = qkvh + 4753;         // 2401
    float* wtile  = attnS + 2401;        // 3104  (32*97)
    float* biasS  = wtile + 3104;        // 2064  (12*172)
    int*   regS   = (int*)(biasS + 2064); // 64
    int*   oidxS  = regS + 64;            // 64

    const int tid = threadIdx.x;
    const int tx  = tid & 31;
    const int ty  = tid >> 5;
    const int w   = blockIdx.x;
    const int b   = w >> 6;
    const int wi  = w & 63;
    const int wr  = wi >> 3;
    const int wc  = wi & 7;

    // ---- preload rel-pos bias table transposed: biasS[h][rel] ----
    for (int i = tid; i < 169 * 12; i += 256) {
        int r = i / 12, h = i - r * 12;
        biasS[h * 172 + r] = table[i];
    }

    // ---- per-token region ids (mask) + output base indices (roll back) ----
    if (tid < NTOK) {
        int tr = tid / 7, tc = tid - tr * 7;
        int gr = wr * 7 + tr, gc = wc * 7 + tc;       // coords in shifted frame
        int rh = (gr < 49) ? 0 : (gr < 53 ? 1 : 2);   // pH-wh=49, pH-sh=53
        int rw = (gc < 49) ? 0 : (gc < 53 ? 1 : 2);
        regS[tid] = rh * 3 + rw;
        int orow = gr + 3; if (orow >= 56) orow -= 56;
        int ocol = gc + 3; if (ocol >= 56) ocol -= 56;
        oidxS[tid] = ((b * 56 + orow) * 56 + ocol) * CDIM;
    }

    // ---- gather window tokens (roll(-3,-3): src = (g+3)%56), float4 ----
    for (int i = tid; i < NTOK * 96; i += 256) {
        int t = i / 96, f = i - t * 96;
        int tr = t / 7, tc = t - tr * 7;
        int sr = wr * 7 + tr + 3; if (sr >= 56) sr -= 56;
        int sc = wc * 7 + tc + 3; if (sc >= 56) sc -= 56;
        const float4* src = (const float4*)(x + ((b * 56 + sr) * 56 + sc) * CDIM);
        ((float4*)(xw + t * CDIM))[f] = src[f];
    }
    __syncthreads();

    // rows owned by this thread: t = ty + 8r, clamped for t >= 49
    int  trow[7];
    bool tval[7];
    #pragma unroll
    for (int r = 0; r < 7; ++r) {
        int t = ty + (r << 3);
        tval[r] = (t < NTOK);
        trow[r] = tval[r] ? t : 0;
    }
    const float qscale = 0.17677669529663687f;  // 1/sqrt(32)

    for (int h = 0; h < NHEADS; ++h) {
        // ================= QKV GEMM for head h =================
        float acc[7][3];
        #pragma unroll
        for (int r = 0; r < 7; ++r) { acc[r][0] = 0.f; acc[r][1] = 0.f; acc[r][2] = 0.f; }

        for (int kc = 0; kc < 12; ++kc) {
            __syncthreads();  // protect wtile (and first-iter phase ordering)
            // stage weight tile: 96 rows (q|k|v of head h) x 32 k, transposed
            for (int i = tid; i < 96 * 32; i += 256) {
                int d = i >> 5, kk = i & 31;
                int s = d >> 5, dd = d & 31;
                int o = s * CDIM + h * 32 + dd;       // global qkv row
                wtile[kk * 97 + d] = qkvw[o * CDIM + kc * 32 + kk];
            }
            __syncthreads();
            #pragma unroll 4
            for (int kk = 0; kk < 32; ++kk) {
                float b0 = wtile[kk * 97 + tx];
                float b1 = wtile[kk * 97 + 32 + tx];
                float b2 = wtile[kk * 97 + 64 + tx];
                #pragma unroll
                for (int r = 0; r < 7; ++r) {
                    float a = xw[trow[r] * CDIM + kc * 32 + kk];
                    acc[r][0] = fmaf(a, b0, acc[r][0]);
                    acc[r][1] = fmaf(a, b1, acc[r][1]);
                    acc[r][2] = fmaf(a, b2, acc[r][2]);
                }
            }
        }
        // write Q (scaled) / K / V
        #pragma unroll
        for (int r = 0; r < 7; ++r) {
            if (tval[r]) {
                int t = trow[r];
                float v0 = acc[r][0] + qkvb[h * 32 + tx];
                float v1 = acc[r][1] + qkvb[CDIM + h * 32 + tx];
                float v2 = acc[r][2] + qkvb[2 * CDIM + h * 32 + tx];
                qkvh[t * 97 + tx]      = v0 * qscale;
                qkvh[t * 97 + 32 + tx] = v1;
                qkvh[t * 97 + 64 + tx] = v2;
            }
        }
        __syncthreads();

        // ================= attn logits = Q K^T + bias + mask =================
        for (int i = tid; i < NTOK * NTOK; i += 256) {
            int ti = i / 49, tj = i - ti * 49;
            const float* qp = qkvh + ti * 97;
            const float* kp = qkvh + tj * 97 + 32;
            float s = 0.f;
            #pragma unroll
            for (int d = 0; d < 32; ++d) s = fmaf(qp[d], kp[d], s);
            int ri = ti / 7, ci = ti - ri * 7;
            int rj = tj / 7, cj = tj - rj * 7;
            int rel = (ri - rj + 6) * 13 + (ci - cj + 6);
            s += biasS[h * 172 + rel];
            if (regS[ti] != regS[tj]) s -= 100.0f;
            attnS[i] = s;
        }
        __syncthreads();

        // ================= softmax, one warp per row-set =================
        for (int row = ty; row < NTOK; row += 8) {
            float v0 = attnS[row * 49 + tx];
            float v1 = (tx < 17) ? attnS[row * 49 + 32 + tx] : -3.0e38f;
            float m = fmaxf(v0, v1);
            #pragma unroll
            for (int off = 16; off; off >>= 1)
                m = fmaxf(m, __shfl_xor_sync(0xffffffffu, m, off));
            float e0 = __expf(v0 - m);
            float e1 = (tx < 17) ? __expf(v1 - m) : 0.f;
            float s = e0 + e1;
            #pragma unroll
            for (int off = 16; off; off >>= 1)
                s += __shfl_xor_sync(0xffffffffu, s, off);
            float inv = 1.0f / s;
            attnS[row * 49 + tx] = e0 * inv;
            if (tx < 17) attnS[row * 49 + 32 + tx] = e1 * inv;
        }
        __syncthreads();

        // ================= out_h = attn @ V =================
        for (int i = tid; i < NTOK * 32; i += 256) {
            int t = i >> 5, d = i & 31;
            const float* ap = attnS + t * 49;
            const float* vp = qkvh + 64 + d;
            float s = 0.f;
            #pragma unroll 7
            for (int m2 = 0; m2 < 49; ++m2) s = fmaf(ap[m2], vp[m2 * 97], s);
            outbuf[t * CDIM + h * 32 + d] = s;
        }
        // next head's kc=0 __syncthreads orders qkvh/attnS reuse
    }
    __syncthreads();

    // ================= output projection, 4 column groups of 96 =================
    for (int cg = 0; cg < 4; ++cg) {
        float acc[7][3];
        #pragma unroll
        for (int r = 0; r < 7; ++r) { acc[r][0] = 0.f; acc[r][1] = 0.f; acc[r][2] = 0.f; }

        for (int kc = 0; kc < 12; ++kc) {
            __syncthreads();
            for (int i = tid; i < 96 * 32; i += 256) {
                int d = i >> 5, kk = i & 31;
                wtile[kk * 97 + d] = projw[(cg * 96 + d) * CDIM + kc * 32 + kk];
            }
            __syncthreads();
            #pragma unroll 4
            for (int kk = 0; kk < 32; ++kk) {
                float b0 = wtile[kk * 97 + tx];
                float b1 = wtile[kk * 97 + 32 + tx];
                float b2 = wtile[kk * 97 + 64 + tx];
                #pragma unroll
                for (int r = 0; r < 7; ++r) {
                    float a = outbuf[trow[r] * CDIM + kc * 32 + kk];
                    acc[r][0] = fmaf(a, b0, acc[r][0]);
                    acc[r][1] = fmaf(a, b1, acc[r][1]);
                    acc[r][2] = fmaf(a, b2, acc[r][2]);
                }
            }
        }
        #pragma unroll
        for (int r = 0; r < 7; ++r) {
            if (tval[r]) {
                int t = trow[r];
                int base = oidxS[t] + cg * 96 + tx;
                out[base]      = acc[r][0] + projb[cg * 96 + tx];
                out[base + 32] = acc[r][1] + projb[cg * 96 + 32 + tx];
                out[base + 64] = acc[r][2] + projb[cg * 96 + 64 + tx];
            }
        }
    }
}

extern "C" void kernel_launch(void* const* d_in, const int* in_sizes, int n_in,
                              void* d_out, int out_size)
{
    const float* x     = (const float*)d_in[0];
    const float* qkvw  = (const float*)d_in[1];
    const float* qkvb  = (const float*)d_in[2];
    const float* projw = (const float*)d_in[3];
    const float* projb = (const float*)d_in[4];
    const float* table = (const float*)d_in[5];
    float* out = (float*)d_out;

    const size_t smem_bytes = 50082u * sizeof(float);  // ~195.6 KB
    cudaFuncSetAttribute(swin_fused_kernel,
                         cudaFuncAttributeMaxDynamicSharedMemorySize,
                         (int)smem_bytes);
    swin_fused_kernel<<<1024, 256, smem_bytes>>>(x, qkvw, qkvb, projw, projb,
                                                 table, out);
}

// round 3
// speedup vs baseline: 1.2560x; 1.2560x over previous
#include <cuda_runtime.h>

// Fused shifted-window attention (Swin), B=16, 56x56, C=384, 12 heads, hd=32,
// window 7x7 (N=49), shift 3. One CTA per window (1024 CTAs, 256 threads).
// Heads processed in pairs; QKV and proj GEMMs use packed fma.rn.f32x2.
//
// Smem (floats, 8B-aligned regions first):
//   xw    [49][388]  window tokens (stride 388: even, f32x2-aligned)
//   wtile 6176       staged weights, interleaved [k/2][col][2]
//   outhS [49][66]   pair head outputs (stride 66: even)
//   qkvh  [49][195]  per-pair Q|K|V (2 heads x 97, stride 195: odd -> no LDS conflicts)
//   attnS [2][49*49] logits/probs for the 2 heads
//   biasP [2][169]   rel-pos bias for pair
//   ints: rowS/colS/regS/oidxS (4*49)
// Total = 43117 floats + 196 ints = 43313 words; allocate 43328.

#define NTOK 49

__device__ __forceinline__ void fma2(unsigned long long& d,
                                     unsigned long long a,
                                     unsigned long long b) {
    asm("fma.rn.f32x2 %0, %1, %2, %0;" : "+l"(d) : "l"(a), "l"(b));
}
__device__ __forceinline__ float lohi_sum(unsigned long long v) {
    float lo = __uint_as_float((unsigned)(v & 0xffffffffull));
    float hi = __uint_as_float((unsigned)(v >> 32));
    return lo + hi;
}

__global__ void __launch_bounds__(256, 1)
swin_fused2_kernel(const float* __restrict__ x,
                   const float* __restrict__ qkvw,
                   const float* __restrict__ qkvb,
                   const float* __restrict__ projw,
                   const float* __restrict__ projb,
                   const float* __restrict__ table,
                   float* __restrict__ out)
{
    extern __shared__ float sm[];
    float* xw    = sm;                    // 19012
    float* wtile = xw + 19012;            // 6176
    float* outhS = wtile + 6176;          // 3234 (49*66)
    float* qkvh  = outhS + 3234;          // 9555 (49*195)
    float* attnS = qkvh + 9555;           // 4802
    float* biasP = attnS + 4802;          // 338
    int*   rowS  = (int*)(biasP + 338);   // 49
    int*   colS  = rowS + 49;             // 49
    int*   regS  = colS + 49;             // 49
    int*   oidxS = regS + 49;             // 49  (ends at word 43313 <= 43328)

    const int tid = threadIdx.x;
    const int tx  = tid & 31;
    const int ty  = tid >> 5;
    const int w   = blockIdx.x;
    const int b   = w >> 6;
    const int wi  = w & 63;
    const int wr  = wi >> 3;
    const int wc  = wi & 7;

    // ---- per-token tables ----
    if (tid < NTOK) {
        int tr = tid / 7, tc = tid - tr * 7;
        rowS[tid] = tr; colS[tid] = tc;
        int gr = wr * 7 + tr, gc = wc * 7 + tc;
        int rh = (gr < 49) ? 0 : (gr < 53 ? 1 : 2);
        int rw = (gc < 49) ? 0 : (gc < 53 ? 1 : 2);
        regS[tid] = rh * 3 + rw;
        int orow = gr + 3; if (orow >= 56) orow -= 56;
        int ocol = gc + 3; if (ocol >= 56) ocol -= 56;
        oidxS[tid] = ((b * 56 + orow) * 56 + ocol) * 384;
    }

    // ---- stage window tokens once (roll(-3,-3)) ----
    for (int i = tid; i < NTOK * 96; i += 256) {
        int t = i / 96, f = i - t * 96;
        int tr = t / 7, tc = t - tr * 7;
        int sr = wr * 7 + tr + 3; if (sr >= 56) sr -= 56;
        int sc = wc * 7 + tc + 3; if (sc >= 56) sc -= 56;
        const float4* src = (const float4*)(x + ((b * 56 + sr) * 56 + sc) * 384);
        ((float4*)(xw + t * 388))[f] = src[f];
    }

    // rows owned by this thread: t = ty + 8r
    int  trow[7];
    bool tval[7];
    #pragma unroll
    for (int r = 0; r < 7; ++r) {
        int t = ty + (r << 3);
        tval[r] = (t < NTOK);
        trow[r] = tval[r] ? t : 0;
    }
    const float qscale = 0.17677669529663687f;

    float pacc[7][12];
    #pragma unroll
    for (int r = 0; r < 7; ++r)
        #pragma unroll
        for (int j = 0; j < 12; ++j) pacc[r][j] = 0.f;

    for (int hp = 0; hp < 6; ++hp) {
        // stage rel-pos bias for this head pair
        for (int i = tid; i < 338; i += 256) {
            int hh = (i >= 169) ? 1 : 0;
            int rel = i - 169 * hh;
            biasP[i] = table[rel * 12 + 2 * hp + hh];
        }

        // ================= QKV GEMM (2 heads, 192 outputs/row) =================
        unsigned long long acc2[7][6];
        #pragma unroll
        for (int r = 0; r < 7; ++r)
            #pragma unroll
            for (int j = 0; j < 6; ++j) acc2[r][j] = 0ull;

        for (int kc = 0; kc < 12; ++kc) {
            __syncthreads();
            // stage 192 cols x 32 k, interleaved [k/2][c][2]
            for (int i = tid; i < 6144; i += 256) {
                int c = i >> 5, kk = i & 31;
                int j = c >> 5, dd = c & 31;
                int s = j >> 1, hh2 = j & 1;
                int o = s * 384 + (2 * hp + hh2) * 32 + dd;
                wtile[(kk >> 1) * 386 + 2 * c + (kk & 1)] =
                    qkvw[o * 384 + kc * 32 + kk];
            }
            __syncthreads();
            #pragma unroll 4
            for (int kp = 0; kp < 16; ++kp) {
                unsigned long long b2[6];
                #pragma unroll
                for (int j = 0; j < 6; ++j)
                    b2[j] = *(const unsigned long long*)
                            (wtile + kp * 386 + 2 * (tx + 32 * j));
                #pragma unroll
                for (int r = 0; r < 7; ++r) {
                    unsigned long long a2 = *(const unsigned long long*)
                        (xw + trow[r] * 388 + kc * 32 + 2 * kp);
                    #pragma unroll
                    for (int j = 0; j < 6; ++j) fma2(acc2[r][j], a2, b2[j]);
                }
            }
        }
        __syncthreads();
        // epilogue: collapse, bias, scale, write qkvh
        #pragma unroll
        for (int r = 0; r < 7; ++r) {
            if (tval[r]) {
                int t = trow[r];
                #pragma unroll
                for (int j = 0; j < 6; ++j) {
                    int s = j >> 1, hh2 = j & 1;
                    float v = lohi_sum(acc2[r][j]);
                    v += qkvb[s * 384 + (2 * hp + hh2) * 32 + tx];
                    if (s == 0) v *= qscale;
                    qkvh[t * 195 + hh2 * 97 + s * 32 + tx] = v;
                }
            }
        }
        __syncthreads();

        // ================= QK^T + bias + mask =================
        #pragma unroll
        for (int hh = 0; hh < 2; ++hh) {
            float s1[7], s2[7];
            #pragma unroll
            for (int r = 0; r < 7; ++r) { s1[r] = 0.f; s2[r] = 0.f; }
            const int koff = hh * 97 + 32;
            for (int d = 0; d < 32; ++d) {
                float k1 = qkvh[tx * 195 + koff + d];
                float k2 = (tx < 17) ? qkvh[(tx + 32) * 195 + koff + d] : 0.f;
                #pragma unroll
                for (int r = 0; r < 7; ++r) {
                    float q = qkvh[trow[r] * 195 + hh * 97 + d];
                    s1[r] = fmaf(q, k1, s1[r]);
                    s2[r] = fmaf(q, k2, s2[r]);
                }
            }
            #pragma unroll
            for (int r = 0; r < 7; ++r) {
                if (!tval[r]) continue;
                int t = trow[r];
                int ri = rowS[t], ci = colS[t], rg = regS[t];
                {
                    int rel = (ri - rowS[tx] + 6) * 13 + (ci - colS[tx] + 6);
                    float v = s1[r] + biasP[hh * 169 + rel];
                    if (rg != regS[tx]) v -= 100.0f;
                    attnS[hh * 2401 + t * 49 + tx] = v;
                }
                if (tx < 17) {
                    int j2 = tx + 32;
                    int rel = (ri - rowS[j2] + 6) * 13 + (ci - colS[j2] + 6);
                    float v = s2[r] + biasP[hh * 169 + rel];
                    if (rg != regS[j2]) v -= 100.0f;
                    attnS[hh * 2401 + t * 49 + j2] = v;
                }
            }
        }
        __syncthreads();

        // ================= softmax: 98 rows over 8 warps =================
        for (int row = ty; row < 98; row += 8) {
            int hh = (row >= 49) ? 1 : 0;
            int rr = row - 49 * hh;
            float* ap = attnS + hh * 2401 + rr * 49;
            float v0 = ap[tx];
            float v1 = (tx < 17) ? ap[32 + tx] : -3.0e38f;
            float m = fmaxf(v0, v1);
            #pragma unroll
            for (int off = 16; off; off >>= 1)
                m = fmaxf(m, __shfl_xor_sync(0xffffffffu, m, off));
            float e0 = __expf(v0 - m);
            float e1 = (tx < 17) ? __expf(v1 - m) : 0.f;
            float s = e0 + e1;
            #pragma unroll
            for (int off = 16; off; off >>= 1)
                s += __shfl_xor_sync(0xffffffffu, s, off);
            float inv = 1.0f / s;
            ap[tx] = e0 * inv;
            if (tx < 17) ap[32 + tx] = e1 * inv;
        }
        __syncthreads();

        // ================= out_pair = attn @ V (both heads) =================
        {
            float o0[7], o1[7];
            #pragma unroll
            for (int r = 0; r < 7; ++r) { o0[r] = 0.f; o1[r] = 0.f; }
            for (int m = 0; m < 49; ++m) {
                float v0 = qkvh[m * 195 + 64 + tx];
                float v1 = qkvh[m * 195 + 97 + 64 + tx];
                #pragma unroll
                for (int r = 0; r < 7; ++r) {
                    float a0 = attnS[trow[r] * 49 + m];
                    float a1 = attnS[2401 + trow[r] * 49 + m];
                    o0[r] = fmaf(a0, v0, o0[r]);
                    o1[r] = fmaf(a1, v1, o1[r]);
                }
            }
            #pragma unroll
            for (int r = 0; r < 7; ++r) {
                if (tval[r]) {
                    outhS[trow[r] * 66 + tx]      = o0[r];
                    outhS[trow[r] * 66 + 32 + tx] = o1[r];
                }
            }
        }
        __syncthreads();

        // ================= proj partial: pacc += outh @ projw_pair^T ==========
        for (int k16 = 0; k16 < 4; ++k16) {
            for (int i = tid; i < 6144; i += 256) {
                int d = i >> 4, kkl = i & 15;
                wtile[(kkl >> 1) * 770 + 2 * d + (kkl & 1)] =
                    projw[d * 384 + hp * 64 + k16 * 16 + kkl];
            }
            __syncthreads();
            #pragma unroll
            for (int jh = 0; jh < 2; ++jh) {
                unsigned long long t2[7][6];
                #pragma unroll
                for (int r = 0; r < 7; ++r)
                    #pragma unroll
                    for (int j = 0; j < 6; ++j) t2[r][j] = 0ull;
                #pragma unroll 4
                for (int kp = 0; kp < 8; ++kp) {
                    unsigned long long b2[6];
                    #pragma unroll
                    for (int j = 0; j < 6; ++j)
                        b2[j] = *(const unsigned long long*)
                                (wtile + kp * 770 + 2 * (tx + 32 * (jh * 6 + j)));
                    #pragma unroll
                    for (int r = 0; r < 7; ++r) {
                        unsigned long long a2 = *(const unsigned long long*)
                            (outhS + trow[r] * 66 + k16 * 16 + 2 * kp);
                        #pragma unroll
                        for (int j = 0; j < 6; ++j) fma2(t2[r][j], a2, b2[j]);
                    }
                }
                #pragma unroll
                for (int r = 0; r < 7; ++r)
                    #pragma unroll
                    for (int j = 0; j < 6; ++j)
                        pacc[r][jh * 6 + j] += lohi_sum(t2[r][j]);
            }
            __syncthreads();
        }
        // trailing sync above also protects outhS/qkvh/attnS reuse next pair
    }

    // ================= final store with proj bias, roll-back scatter =========
    #pragma unroll
    for (int r = 0; r < 7; ++r) {
        if (!tval[r]) continue;
        int base = oidxS[trow[r]];
        #pragma unroll
        for (int j = 0; j < 12; ++j) {
            int c = tx + 32 * j;
            out[base + c] = pacc[r][j] + projb[c];
        }
    }
}

extern "C" void kernel_launch(void* const* d_in, const int* in_sizes, int n_in,
                              void* d_out, int out_size)
{
    const float* x     = (const float*)d_in[0];
    const float* qkvw  = (const float*)d_in[1];
    const float* qkvb  = (const float*)d_in[2];
    const float* projw = (const float*)d_in[3];
    const float* projb = (const float*)d_in[4];
    const float* table = (const float*)d_in[5];
    float* out = (float*)d_out;

    const size_t smem_bytes = 43328u * sizeof(float);  // 169.25 KB (need 43313)
    cudaFuncSetAttribute(swin_fused2_kernel,
                         cudaFuncAttributeMaxDynamicSharedMemorySize,
                         (int)smem_bytes);
    swin_fused2_kernel<<<1024, 256, smem_bytes>>>(x, qkvw, qkvb, projw, projb,
                                                  table, out);
}

// round 6
// speedup vs baseline: 2.4698x; 1.9664x over previous
#include <cuda_runtime.h>
#include <cuda_bf16.h>
#include <cstdint>

// ============================================================================
// Shifted-window attention, 3-kernel pipeline (no 'a'-feature PTX):
//   K1: g_qkv = X @ qkvw^T + qkvb      (mma.sync bf16 3-term split GEMM)
//   K2: per-window attention -> g_attno (FFMA2)
//   K3: out  = g_attno @ projw^T + projb (same GEMM)
// Roll gather on K2 input == roll scatter on K2 output (same index map), so
// K1/K3 run in natural token order with zero gather/scatter.
// ============================================================================

#define KDIM 384
#define NTOKENS 50176   // 16*56*56 = 392*128

static __device__ float g_qkv[(size_t)NTOKENS * 1152];
static __device__ float g_attno[(size_t)NTOKENS * 384];

__device__ __forceinline__ uint32_t smem_u32(const void* p) {
    uint32_t a;
    asm("{ .reg .u64 t; cvta.to.shared.u64 t, %1; cvt.u32.u64 %0, t; }"
        : "=r"(a) : "l"(p));
    return a;
}

#define LDM4(r0, r1, r2, r3, addr)                                           \
    asm volatile("ldmatrix.sync.aligned.m8n8.x4.shared.b16 {%0,%1,%2,%3}, [%4];" \
                 : "=r"(r0), "=r"(r1), "=r"(r2), "=r"(r3) : "r"(addr))

#define MMA_BF16(c, a, b)                                                    \
    asm volatile("mma.sync.aligned.m16n8k16.row.col.f32.bf16.bf16.f32 "      \
                 "{%0,%1,%2,%3}, {%4,%5,%6,%7}, {%8,%9}, {%0,%1,%2,%3};"     \
                 : "+f"((c)[0]), "+f"((c)[1]), "+f"((c)[2]), "+f"((c)[3])    \
                 : "r"((a)[0]), "r"((a)[1]), "r"((a)[2]), "r"((a)[3]),       \
                   "r"((b)[0]), "r"((b)[1]))

__device__ __forceinline__ void cvt_split(float x, unsigned short& h,
                                          unsigned short& l) {
    __nv_bfloat16 bh = __float2bfloat16_rn(x);
    h = __bfloat16_as_ushort(bh);
    l = __bfloat16_as_ushort(__float2bfloat16_rn(x - __bfloat162float(bh)));
}

__device__ __forceinline__ void fma2(unsigned long long& d,
                                     unsigned long long a, unsigned long long b) {
    asm("fma.rn.f32x2 %0, %1, %2, %0;" : "+l"(d) : "l"(a), "l"(b));
}
__device__ __forceinline__ unsigned long long pack2(float a) {
    unsigned long long v;
    asm("mov.b64 %0, {%1, %1};" : "=l"(v) : "f"(a));
    return v;
}
__device__ __forceinline__ float2 unpack2(unsigned long long v) {
    float lo, hi;
    asm("mov.b64 {%0, %1}, %2;" : "=f"(lo), "=f"(hi) : "l"(v));
    return make_float2(lo, hi);
}
__device__ __forceinline__ float lohi_sum(unsigned long long v) {
    float2 f = unpack2(v);
    return f.x + f.y;
}

// ============================================================================
// K1/K3: C[M, ncols] = A[M,384] @ W[ncols,384]^T + bias  (bf16 3-term split)
// grid (M/128, ncols/128), block 256 (8 warps, 4M x 2N). K-chunk 64, 6 chunks.
// smem tiles stride 72 bf16 (144 B): row holds 64 elems + 8 pad; 144 B row
// stride advances the 16-byte phase by 1 per row -> ldmatrix conflict-free.
// Tiles in dynamic smem: 4 x 128 x 72 x 2 B = 73728 B.
// ============================================================================
#define GSTRIDE 72
#define GTILE_B (128 * GSTRIDE * 2)      // 18432 bytes per tile
#define GSMEM_BYTES (4 * GTILE_B)        // 73728

__global__ void __launch_bounds__(256, 1)
gemm_bf16x3_kernel(const float* __restrict__ A, const float* __restrict__ W,
                   const float* __restrict__ bias, float* __restrict__ C,
                   int ncols, int qflag)
{
    extern __shared__ __align__(16) unsigned short gsm[];
    unsigned short* Ahi = gsm;
    unsigned short* Alo = gsm + 128 * GSTRIDE;
    unsigned short* Bhi = gsm + 2 * 128 * GSTRIDE;
    unsigned short* Blo = gsm + 3 * 128 * GSTRIDE;

    const int tid  = threadIdx.x;
    const int lane = tid & 31;
    const int wid  = tid >> 5;
    const int wm   = wid & 3;          // 0..3 -> M groups of 32
    const int wn   = wid >> 2;         // 0..1 -> N groups of 64
    const int mbase = blockIdx.x * 128;
    const int nbase = blockIdx.y * 128;

    const uint32_t sAhi = smem_u32(Ahi), sAlo = smem_u32(Alo);
    const uint32_t sBhi = smem_u32(Bhi), sBlo = smem_u32(Blo);

    // lane-dependent ldmatrix offsets (bytes), row stride 144 B
    const int lr = lane & 7, lq = lane >> 3;
    const uint32_t aoff =
        (uint32_t)((((lq & 1) * 8 + lr) * GSTRIDE + (lq >> 1) * 8) * 2);
    const uint32_t boff =
        (uint32_t)((((lq >> 1) * 8 + lr) * GSTRIDE + (lq & 1) * 8) * 2);

    float c[2][8][4];
    #pragma unroll
    for (int mt = 0; mt < 2; ++mt)
        #pragma unroll
        for (int nt = 0; nt < 8; ++nt)
            #pragma unroll
            for (int i = 0; i < 4; ++i) c[mt][nt][i] = 0.f;

    const int srow = tid >> 1;           // 0..127
    const int skh  = (tid & 1) * 32;     // k-half within 64 chunk

    for (int kc = 0; kc < 6; ++kc) {
        __syncthreads();
        // ---- stage A and B (hi/lo split), 32 k-values per thread each ----
        {
            const float4* ap = (const float4*)(A + (size_t)(mbase + srow) * KDIM
                                               + kc * 64 + skh);
            const float4* bp = (const float4*)(W + (size_t)(nbase + srow) * KDIM
                                               + kc * 64 + skh);
            #pragma unroll
            for (int q = 0; q < 8; ++q) {
                float4 va = ap[q];
                float4 vb = bp[q];
                ushort4 ah, al, bh, bl;
                cvt_split(va.x, ah.x, al.x); cvt_split(va.y, ah.y, al.y);
                cvt_split(va.z, ah.z, al.z); cvt_split(va.w, ah.w, al.w);
                cvt_split(vb.x, bh.x, bl.x); cvt_split(vb.y, bh.y, bl.y);
                cvt_split(vb.z, bh.z, bl.z); cvt_split(vb.w, bh.w, bl.w);
                int idx = srow * GSTRIDE + skh + q * 4;
                *(ushort4*)(Ahi + idx) = ah;
                *(ushort4*)(Alo + idx) = al;
                *(ushort4*)(Bhi + idx) = bh;
                *(ushort4*)(Blo + idx) = bl;
            }
        }
        __syncthreads();

        // ---- 4 k16 steps ----
        #pragma unroll
        for (int ks = 0; ks < 4; ++ks) {
            const uint32_t kb = (uint32_t)(ks * 32);   // 16 bf16 = 32 B
            uint32_t ah[2][4], al[2][4];
            #pragma unroll
            for (int mt = 0; mt < 2; ++mt) {
                uint32_t base = (uint32_t)((wm * 32 + mt * 16) * (GSTRIDE * 2)) + kb;
                LDM4(ah[mt][0], ah[mt][1], ah[mt][2], ah[mt][3], sAhi + base + aoff);
                LDM4(al[mt][0], al[mt][1], al[mt][2], al[mt][3], sAlo + base + aoff);
            }
            uint32_t bh[8][2], bl[8][2];
            #pragma unroll
            for (int ntp = 0; ntp < 4; ++ntp) {
                uint32_t base = (uint32_t)((wn * 64 + ntp * 16) * (GSTRIDE * 2)) + kb;
                LDM4(bh[2*ntp][0], bh[2*ntp][1], bh[2*ntp+1][0], bh[2*ntp+1][1],
                     sBhi + base + boff);
                LDM4(bl[2*ntp][0], bl[2*ntp][1], bl[2*ntp+1][0], bl[2*ntp+1][1],
                     sBlo + base + boff);
            }
            #pragma unroll
            for (int mt = 0; mt < 2; ++mt)
                #pragma unroll
                for (int nt = 0; nt < 8; ++nt) {
                    MMA_BF16(c[mt][nt], ah[mt], bh[nt]);
                    MMA_BF16(c[mt][nt], ah[mt], bl[nt]);
                    MMA_BF16(c[mt][nt], al[mt], bh[nt]);
                }
        }
    }

    // ---- epilogue ----
    const float qscale = 0.17677669529663687f;
    #pragma unroll
    for (int mt = 0; mt < 2; ++mt) {
        #pragma unroll
        for (int nt = 0; nt < 8; ++nt) {
            int row0 = mbase + wm * 32 + mt * 16 + (lane >> 2);
            int col  = nbase + wn * 64 + nt * 8 + (lane & 3) * 2;
            float sc = (qflag && col < 384) ? qscale : 1.0f;
            float b0 = __ldg(bias + col), b1 = __ldg(bias + col + 1);
            float2 v0 = make_float2((c[mt][nt][0] + b0) * sc,
                                    (c[mt][nt][1] + b1) * sc);
            float2 v1 = make_float2((c[mt][nt][2] + b0) * sc,
                                    (c[mt][nt][3] + b1) * sc);
            *(float2*)(C + (size_t)row0 * ncols + col) = v0;
            *(float2*)(C + (size_t)(row0 + 8) * ncols + col) = v1;
        }
    }
}

// ============================================================================
// K2: per-window attention. grid 1024, block 256.
// smem floats: qkvh[49][194] | attnS[2][49*50] | biasP[338] | ints (4*49)
// ============================================================================
#define K2_QKVH  0
#define K2_ATTN  9506
#define K2_BIAS  14406
#define K2_INTS  14744
#define K2_WORDS 14976   // 59904 bytes

__global__ void __launch_bounds__(256, 2)
swin_attn_kernel(const float* __restrict__ qkv,
                 const float* __restrict__ table,
                 float* __restrict__ attno)
{
    extern __shared__ float sf[];
    float* qkvh  = sf + K2_QKVH;           // stride 194
    float* attnS = sf + K2_ATTN;           // 2 x [49][50]
    float* biasP = sf + K2_BIAS;           // 2 x 169
    int*   tokS  = (int*)(sf + K2_INTS);
    int*   regS  = tokS + 49;
    int*   rowS  = regS + 49;
    int*   colS  = rowS + 49;

    const int tid = threadIdx.x;
    const int tx  = tid & 31;
    const int ty  = tid >> 5;
    const int w   = blockIdx.x;
    const int b   = w >> 6;
    const int wi  = w & 63;
    const int wr  = wi >> 3;
    const int wc  = wi & 7;

    if (tid < 49) {
        int tr = tid / 7, tc = tid - tr * 7;
        rowS[tid] = tr; colS[tid] = tc;
        int gr = wr * 7 + tr, gc = wc * 7 + tc;
        int rh = (gr < 49) ? 0 : (gr < 53 ? 1 : 2);
        int rw = (gc < 49) ? 0 : (gc < 53 ? 1 : 2);
        regS[tid] = rh * 3 + rw;
        int sr = gr + 3; if (sr >= 56) sr -= 56;
        int sc = gc + 3; if (sc >= 56) sc -= 56;
        tokS[tid] = (b * 56 + sr) * 56 + sc;
    }
    __syncthreads();

    int  trow[7];
    bool tval[7];
    #pragma unroll
    for (int r = 0; r < 7; ++r) {
        int t = ty + (r << 3);
        tval[r] = (t < 49);
        trow[r] = tval[r] ? t : 0;
    }

    for (int hp = 0; hp < 6; ++hp) {
        for (int i = tid; i < 338; i += 256) {
            int hh = (i >= 169) ? 1 : 0;
            biasP[i] = table[(i - 169 * hh) * 12 + 2 * hp + hh];
        }
        for (int i = tid; i < 49 * 96; i += 256) {
            int t = i / 96, f2 = i - t * 96;
            int s = f2 >> 5, d2 = f2 & 31;
            const float2* src = (const float2*)
                (qkv + (size_t)tokS[t] * 1152 + s * 384 + hp * 64 + 2 * d2);
            *(float2*)(qkvh + t * 194 + s * 64 + 2 * d2) = *src;
        }
        __syncthreads();

        // ---- QK^T + bias + mask ----
        #pragma unroll
        for (int hh = 0; hh < 2; ++hh) {
            unsigned long long a1[7], a2[7];
            #pragma unroll
            for (int r = 0; r < 7; ++r) { a1[r] = 0ull; a2[r] = 0ull; }
            const int j2 = (tx < 17) ? (tx + 32) : 0;
            #pragma unroll 4
            for (int dp = 0; dp < 16; ++dp) {
                unsigned long long k1 = *(const unsigned long long*)
                    (qkvh + tx * 194 + 64 + hh * 32 + 2 * dp);
                unsigned long long k2 = *(const unsigned long long*)
                    (qkvh + j2 * 194 + 64 + hh * 32 + 2 * dp);
                #pragma unroll
                for (int r = 0; r < 7; ++r) {
                    unsigned long long q2 = *(const unsigned long long*)
                        (qkvh + trow[r] * 194 + hh * 32 + 2 * dp);
                    fma2(a1[r], q2, k1);
                    fma2(a2[r], q2, k2);
                }
            }
            #pragma unroll
            for (int r = 0; r < 7; ++r) {
                if (!tval[r]) continue;
                int t = trow[r];
                int ri = rowS[t], ci = colS[t], rg = regS[t];
                {
                    int rel = (ri - rowS[tx] + 6) * 13 + (ci - colS[tx] + 6);
                    float v = lohi_sum(a1[r]) + biasP[hh * 169 + rel];
                    if (rg != regS[tx]) v -= 100.0f;
                    attnS[hh * 2450 + t * 50 + tx] = v;
                }
                if (tx < 17) {
                    int rel = (ri - rowS[j2] + 6) * 13 + (ci - colS[j2] + 6);
                    float v = lohi_sum(a2[r]) + biasP[hh * 169 + rel];
                    if (rg != regS[j2]) v -= 100.0f;
                    attnS[hh * 2450 + t * 50 + j2] = v;
                }
            }
        }
        __syncthreads();

        // ---- softmax ----
        for (int row = ty; row < 98; row += 8) {
            int hh = (row >= 49) ? 1 : 0;
            float* ap = attnS + hh * 2450 + (row - 49 * hh) * 50;
            float v0 = ap[tx];
            float v1 = (tx < 17) ? ap[32 + tx] : -3.0e38f;
            float m = fmaxf(v0, v1);
            #pragma unroll
            for (int off = 16; off; off >>= 1)
                m = fmaxf(m, __shfl_xor_sync(0xffffffffu, m, off));
            float e0 = __expf(v0 - m);
            float e1 = (tx < 17) ? __expf(v1 - m) : 0.f;
            float s = e0 + e1;
            #pragma unroll
            for (int off = 16; off; off >>= 1)
                s += __shfl_xor_sync(0xffffffffu, s, off);
            float inv = 1.0f / s;
            ap[tx] = e0 * inv;
            if (tx < 17) ap[32 + tx] = e1 * inv;
        }
        __syncthreads();

        // ---- out = attn @ V ----
        {
            const int hh = tx >> 4, dp = tx & 15;
            unsigned long long o2[7];
            #pragma unroll
            for (int r = 0; r < 7; ++r) o2[r] = 0ull;
            const float* aB = attnS + hh * 2450;
            for (int m = 0; m < 49; ++m) {
                unsigned long long v2 = *(const unsigned long long*)
                    (qkvh + m * 194 + 128 + hh * 32 + 2 * dp);
                #pragma unroll
                for (int r = 0; r < 7; ++r) {
                    unsigned long long ap2 = pack2(aB[trow[r] * 50 + m]);
                    fma2(o2[r], ap2, v2);
                }
            }
            #pragma unroll
            for (int r = 0; r < 7; ++r) {
                if (tval[r]) {
                    float2 f = unpack2(o2[r]);
                    *(float2*)(attno + (size_t)tokS[trow[r]] * 384
                               + (2 * hp + hh) * 32 + 2 * dp) = f;
                }
            }
        }
        __syncthreads();
    }
}

// ============================================================================
extern "C" void kernel_launch(void* const* d_in, const int* in_sizes, int n_in,
                              void* d_out, int out_size)
{
    const float* x     = (const float*)d_in[0];
    const float* qkvw  = (const float*)d_in[1];
    const float* qkvb  = (const float*)d_in[2];
    const float* projw = (const float*)d_in[3];
    const float* projb = (const float*)d_in[4];
    const float* table = (const float*)d_in[5];
    float* out = (float*)d_out;

    float *gq, *ga;
    cudaGetSymbolAddress((void**)&gq, g_qkv);
    cudaGetSymbolAddress((void**)&ga, g_attno);

    cudaFuncSetAttribute(gemm_bf16x3_kernel,
                         cudaFuncAttributeMaxDynamicSharedMemorySize, GSMEM_BYTES);
    cudaFuncSetAttribute(swin_attn_kernel,
                         cudaFuncAttributeMaxDynamicSharedMemorySize,
                         K2_WORDS * (int)sizeof(float));

    gemm_bf16x3_kernel<<<dim3(392, 9), 256, GSMEM_BYTES>>>(x, qkvw, qkvb, gq, 1152, 1);
    swin_attn_kernel<<<1024, 256, K2_WORDS * sizeof(float)>>>(gq, table, ga);
    gemm_bf16x3_kernel<<<dim3(392, 3), 256, GSMEM_BYTES>>>(ga, projw, projb, out, 384, 0);
}

// round 7
// speedup vs baseline: 3.5767x; 1.4482x over previous
#include <cuda_runtime.h>
#include <cuda_bf16.h>
#include <cstdint>

// ============================================================================
// Shifted-window attention pipeline:
//   K0: split X / qkvw / projw into bf16 (hi, lo) pairs        (elementwise)
//   K1: g_qkv = X @ qkvw^T + qkvb    (mma.sync bf16 3-term, cp.async 2-stage)
//   K2: per-window attention -> bf16 hi/lo attn output          (FFMA2)
//   K3: out = attno @ projw^T + projb (same GEMM, bf16 inputs direct)
// ============================================================================

#define KDIM 384
#define NTOKENS 50176   // 16*56*56 = 392*128

static __device__ float          g_qkv[(size_t)NTOKENS * 1152];
static __device__ unsigned short g_xhi[(size_t)NTOKENS * 384];
static __device__ unsigned short g_xlo[(size_t)NTOKENS * 384];
static __device__ unsigned short g_ahi[(size_t)NTOKENS * 384];
static __device__ unsigned short g_alo[(size_t)NTOKENS * 384];
static __device__ unsigned short g_whi[1152 * 384];
static __device__ unsigned short g_wlo[1152 * 384];
static __device__ unsigned short g_phi[384 * 384];
static __device__ unsigned short g_plo[384 * 384];

__device__ __forceinline__ uint32_t smem_u32(const void* p) {
    uint32_t a;
    asm("{ .reg .u64 t; cvta.to.shared.u64 t, %1; cvt.u32.u64 %0, t; }"
        : "=r"(a) : "l"(p));
    return a;
}
#define LDM4(r0, r1, r2, r3, addr)                                           \
    asm volatile("ldmatrix.sync.aligned.m8n8.x4.shared.b16 {%0,%1,%2,%3}, [%4];" \
                 : "=r"(r0), "=r"(r1), "=r"(r2), "=r"(r3) : "r"(addr))
#define MMA_BF16(c, a, b)                                                    \
    asm volatile("mma.sync.aligned.m16n8k16.row.col.f32.bf16.bf16.f32 "      \
                 "{%0,%1,%2,%3}, {%4,%5,%6,%7}, {%8,%9}, {%0,%1,%2,%3};"     \
                 : "+f"((c)[0]), "+f"((c)[1]), "+f"((c)[2]), "+f"((c)[3])    \
                 : "r"((a)[0]), "r"((a)[1]), "r"((a)[2]), "r"((a)[3]),       \
                   "r"((b)[0]), "r"((b)[1]))
#define CPA16(dst, src)                                                      \
    asm volatile("cp.async.ca.shared.global [%0], [%1], 16;" :: "r"(dst), "l"(src))
#define CPA_COMMIT() asm volatile("cp.async.commit_group;")
#define CPA_WAIT1()  asm volatile("cp.async.wait_group 1;")
#define CPA_WAIT0()  asm volatile("cp.async.wait_group 0;")

__device__ __forceinline__ void cvt_split(float x, unsigned short& h,
                                          unsigned short& l) {
    __nv_bfloat16 bh = __float2bfloat16_rn(x);
    h = __bfloat16_as_ushort(bh);
    l = __bfloat16_as_ushort(__float2bfloat16_rn(x - __bfloat162float(bh)));
}
__device__ __forceinline__ void fma2(unsigned long long& d,
                                     unsigned long long a, unsigned long long b) {
    asm("fma.rn.f32x2 %0, %1, %2, %0;" : "+l"(d) : "l"(a), "l"(b));
}
__device__ __forceinline__ unsigned long long pack2(float a) {
    unsigned long long v;
    asm("mov.b64 %0, {%1, %1};" : "=l"(v) : "f"(a));
    return v;
}
__device__ __forceinline__ float2 unpack2(unsigned long long v) {
    float lo, hi;
    asm("mov.b64 {%0, %1}, %2;" : "=f"(lo), "=f"(hi) : "l"(v));
    return make_float2(lo, hi);
}
__device__ __forceinline__ float lohi_sum(unsigned long long v) {
    float2 f = unpack2(v);
    return f.x + f.y;
}

// ============================================================================
// K0: fp32 -> bf16 hi/lo split, float4 granularity
// ============================================================================
__global__ void __launch_bounds__(256)
split_bf16_kernel(const float4* __restrict__ in, ushort4* __restrict__ hi,
                  ushort4* __restrict__ lo, int n4)
{
    int i = blockIdx.x * 256 + threadIdx.x;
    if (i >= n4) return;
    float4 v = in[i];
    ushort4 h, l;
    cvt_split(v.x, h.x, l.x);
    cvt_split(v.y, h.y, l.y);
    cvt_split(v.z, h.z, l.z);
    cvt_split(v.w, h.w, l.w);
    hi[i] = h;
    lo[i] = l;
}

// ============================================================================
// K1/K3: C[M, ncols] = A @ B^T + bias, A/B pre-split bf16 hi/lo.
// grid (M/128, ncols/128), block 256 (8 warps, 4M x 2N), K-chunk 64,
// cp.async 2-stage double buffer. smem row stride 72 bf16 (144 B) ->
// ldmatrix conflict-free (16B phase advance per row).
// ============================================================================
#define GSTR 72
#define TILE_US (128 * GSTR)          // 9216 ushorts per tile
#define STAGE_US (4 * TILE_US)        // Ahi|Alo|Bhi|Blo
#define GSMEM_BYTES (2 * STAGE_US * 2) // 147456 B

__global__ void __launch_bounds__(256, 1)
gemm_bf16x3_kernel(const unsigned short* __restrict__ Ahi_g,
                   const unsigned short* __restrict__ Alo_g,
                   const unsigned short* __restrict__ Bhi_g,
                   const unsigned short* __restrict__ Blo_g,
                   const float* __restrict__ bias, float* __restrict__ C,
                   int ncols, int qflag)
{
    extern __shared__ __align__(16) unsigned short gsm[];

    const int tid  = threadIdx.x;
    const int lane = tid & 31;
    const int wid  = tid >> 5;
    const int wm   = wid & 3;
    const int wn   = wid >> 2;
    const int mbase = blockIdx.x * 128;
    const int nbase = blockIdx.y * 128;

    // per-thread cp.async source/dest: 4 chunks of 16B per tile
    // chunk c (0..1023): row = c>>3, c8 = c&7
    const uint32_t sbase = smem_u32(gsm);

    // lane-dependent ldmatrix offsets (bytes)
    const int lr = lane & 7, lq = lane >> 3;
    const uint32_t aoff =
        (uint32_t)((((lq & 1) * 8 + lr) * GSTR + (lq >> 1) * 8) * 2);
    const uint32_t boff =
        (uint32_t)((((lq >> 1) * 8 + lr) * GSTR + (lq & 1) * 8) * 2);

    float c[2][8][4];
    #pragma unroll
    for (int mt = 0; mt < 2; ++mt)
        #pragma unroll
        for (int nt = 0; nt < 8; ++nt)
            #pragma unroll
            for (int i = 0; i < 4; ++i) c[mt][nt][i] = 0.f;

    // ---- prefetch helper (stage s buffer, k-chunk kc) ----
    auto prefetch = [&](int sbuf, int kc) {
        const uint32_t st = sbase + (uint32_t)sbuf * (STAGE_US * 2);
        #pragma unroll
        for (int j = 0; j < 4; ++j) {
            int cch = tid + 256 * j;
            int row = cch >> 3, c8 = cch & 7;
            uint32_t doff = (uint32_t)(row * 144 + c8 * 16);
            size_t aidx = (size_t)(mbase + row) * KDIM + kc * 64 + c8 * 8;
            size_t bidx = (size_t)(nbase + row) * KDIM + kc * 64 + c8 * 8;
            CPA16(st + doff, Ahi_g + aidx);
            CPA16(st + TILE_US * 2 + doff, Alo_g + aidx);
            CPA16(st + TILE_US * 4 + doff, Bhi_g + bidx);
            CPA16(st + TILE_US * 6 + doff, Blo_g + bidx);
        }
        CPA_COMMIT();
    };

    prefetch(0, 0);

    for (int kc = 0; kc < 6; ++kc) {
        if (kc + 1 < 6) {
            prefetch((kc + 1) & 1, kc + 1);
            CPA_WAIT1();
        } else {
            CPA_WAIT0();
        }
        __syncthreads();

        const uint32_t st = sbase + (uint32_t)(kc & 1) * (STAGE_US * 2);
        const uint32_t sAhi = st;
        const uint32_t sAlo = st + TILE_US * 2;
        const uint32_t sBhi = st + TILE_US * 4;
        const uint32_t sBlo = st + TILE_US * 6;

        #pragma unroll
        for (int ks = 0; ks < 4; ++ks) {
            const uint32_t kb = (uint32_t)(ks * 32);
            uint32_t ah[2][4], al[2][4];
            #pragma unroll
            for (int mt = 0; mt < 2; ++mt) {
                uint32_t base = (uint32_t)((wm * 32 + mt * 16) * (GSTR * 2)) + kb;
                LDM4(ah[mt][0], ah[mt][1], ah[mt][2], ah[mt][3], sAhi + base + aoff);
                LDM4(al[mt][0], al[mt][1], al[mt][2], al[mt][3], sAlo + base + aoff);
            }
            uint32_t bh[8][2], bl[8][2];
            #pragma unroll
            for (int ntp = 0; ntp < 4; ++ntp) {
                uint32_t base = (uint32_t)((wn * 64 + ntp * 16) * (GSTR * 2)) + kb;
                LDM4(bh[2*ntp][0], bh[2*ntp][1], bh[2*ntp+1][0], bh[2*ntp+1][1],
                     sBhi + base + boff);
                LDM4(bl[2*ntp][0], bl[2*ntp][1], bl[2*ntp+1][0], bl[2*ntp+1][1],
                     sBlo + base + boff);
            }
            #pragma unroll
            for (int mt = 0; mt < 2; ++mt)
                #pragma unroll
                for (int nt = 0; nt < 8; ++nt) {
                    MMA_BF16(c[mt][nt], ah[mt], bh[nt]);
                    MMA_BF16(c[mt][nt], ah[mt], bl[nt]);
                    MMA_BF16(c[mt][nt], al[mt], bh[nt]);
                }
        }
        __syncthreads();
    }

    // ---- epilogue ----
    const float qscale = 0.17677669529663687f;
    #pragma unroll
    for (int mt = 0; mt < 2; ++mt) {
        #pragma unroll
        for (int nt = 0; nt < 8; ++nt) {
            int row0 = mbase + wm * 32 + mt * 16 + (lane >> 2);
            int col  = nbase + wn * 64 + nt * 8 + (lane & 3) * 2;
            float sc = (qflag && col < 384) ? qscale : 1.0f;
            float b0 = __ldg(bias + col), b1 = __ldg(bias + col + 1);
            float2 v0 = make_float2((c[mt][nt][0] + b0) * sc,
                                    (c[mt][nt][1] + b1) * sc);
            float2 v1 = make_float2((c[mt][nt][2] + b0) * sc,
                                    (c[mt][nt][3] + b1) * sc);
            *(float2*)(C + (size_t)row0 * ncols + col) = v0;
            *(float2*)(C + (size_t)(row0 + 8) * ncols + col) = v1;
        }
    }
}

// ============================================================================
// K2: per-window attention. grid 1024, block 256. Output: bf16 hi/lo arrays.
// ============================================================================
#define K2_QKVH  0
#define K2_ATTN  9506
#define K2_BIAS  14406
#define K2_INTS  14744
#define K2_WORDS 14976

__global__ void __launch_bounds__(256, 2)
swin_attn_kernel(const float* __restrict__ qkv,
                 const float* __restrict__ table,
                 unsigned short* __restrict__ ahi,
                 unsigned short* __restrict__ alo)
{
    extern __shared__ float sf[];
    float* qkvh  = sf + K2_QKVH;           // stride 194
    float* attnS = sf + K2_ATTN;           // 2 x [49][50]
    float* biasP = sf + K2_BIAS;
    int*   tokS  = (int*)(sf + K2_INTS);
    int*   regS  = tokS + 49;
    int*   rowS  = regS + 49;
    int*   colS  = rowS + 49;

    const int tid = threadIdx.x;
    const int tx  = tid & 31;
    const int ty  = tid >> 5;
    const int w   = blockIdx.x;
    const int b   = w >> 6;
    const int wi  = w & 63;
    const int wr  = wi >> 3;
    const int wc  = wi & 7;

    if (tid < 49) {
        int tr = tid / 7, tc = tid - tr * 7;
        rowS[tid] = tr; colS[tid] = tc;
        int gr = wr * 7 + tr, gc = wc * 7 + tc;
        int rh = (gr < 49) ? 0 : (gr < 53 ? 1 : 2);
        int rw = (gc < 49) ? 0 : (gc < 53 ? 1 : 2);
        regS[tid] = rh * 3 + rw;
        int sr = gr + 3; if (sr >= 56) sr -= 56;
        int sc = gc + 3; if (sc >= 56) sc -= 56;
        tokS[tid] = (b * 56 + sr) * 56 + sc;
    }
    __syncthreads();

    int  trow[7];
    bool tval[7];
    #pragma unroll
    for (int r = 0; r < 7; ++r) {
        int t = ty + (r << 3);
        tval[r] = (t < 49);
        trow[r] = tval[r] ? t : 0;
    }

    for (int hp = 0; hp < 6; ++hp) {
        for (int i = tid; i < 338; i += 256) {
            int hh = (i >= 169) ? 1 : 0;
            biasP[i] = table[(i - 169 * hh) * 12 + 2 * hp + hh];
        }
        for (int i = tid; i < 49 * 96; i += 256) {
            int t = i / 96, f2 = i - t * 96;
            int s = f2 >> 5, d2 = f2 & 31;
            const float2* src = (const float2*)
                (qkv + (size_t)tokS[t] * 1152 + s * 384 + hp * 64 + 2 * d2);
            *(float2*)(qkvh + t * 194 + s * 64 + 2 * d2) = *src;
        }
        __syncthreads();

        // ---- QK^T + bias + mask ----
        #pragma unroll
        for (int hh = 0; hh < 2; ++hh) {
            unsigned long long a1[7], a2[7];
            #pragma unroll
            for (int r = 0; r < 7; ++r) { a1[r] = 0ull; a2[r] = 0ull; }
            const int j2 = (tx < 17) ? (tx + 32) : 0;
            #pragma unroll 4
            for (int dp = 0; dp < 16; ++dp) {
                unsigned long long k1 = *(const unsigned long long*)
                    (qkvh + tx * 194 + 64 + hh * 32 + 2 * dp);
                unsigned long long k2 = *(const unsigned long long*)
                    (qkvh + j2 * 194 + 64 + hh * 32 + 2 * dp);
                #pragma unroll
                for (int r = 0; r < 7; ++r) {
                    unsigned long long q2 = *(const unsigned long long*)
                        (qkvh + trow[r] * 194 + hh * 32 + 2 * dp);
                    fma2(a1[r], q2, k1);
                    fma2(a2[r], q2, k2);
                }
            }
            #pragma unroll
            for (int r = 0; r < 7; ++r) {
                if (!tval[r]) continue;
                int t = trow[r];
                int ri = rowS[t], ci = colS[t], rg = regS[t];
                {
                    int rel = (ri - rowS[tx] + 6) * 13 + (ci - colS[tx] + 6);
                    float v = lohi_sum(a1[r]) + biasP[hh * 169 + rel];
                    if (rg != regS[tx]) v -= 100.0f;
                    attnS[hh * 2450 + t * 50 + tx] = v;
                }
                if (tx < 17) {
                    int rel = (ri - rowS[j2] + 6) * 13 + (ci - colS[j2] + 6);
                    float v = lohi_sum(a2[r]) + biasP[hh * 169 + rel];
                    if (rg != regS[j2]) v -= 100.0f;
                    attnS[hh * 2450 + t * 50 + j2] = v;
                }
            }
        }
        __syncthreads();

        // ---- softmax ----
        for (int row = ty; row < 98; row += 8) {
            int hh = (row >= 49) ? 1 : 0;
            float* ap = attnS + hh * 2450 + (row - 49 * hh) * 50;
            float v0 = ap[tx];
            float v1 = (tx < 17) ? ap[32 + tx] : -3.0e38f;
            float m = fmaxf(v0, v1);
            #pragma unroll
            for (int off = 16; off; off >>= 1)
                m = fmaxf(m, __shfl_xor_sync(0xffffffffu, m, off));
            float e0 = __expf(v0 - m);
            float e1 = (tx < 17) ? __expf(v1 - m) : 0.f;
            float s = e0 + e1;
            #pragma unroll
            for (int off = 16; off; off >>= 1)
                s += __shfl_xor_sync(0xffffffffu, s, off);
            float inv = 1.0f / s;
            ap[tx] = e0 * inv;
            if (tx < 17) ap[32 + tx] = e1 * inv;
        }
        __syncthreads();

        // ---- out = attn @ V, write bf16 hi/lo ----
        {
            const int hh = tx >> 4, dp = tx & 15;
            unsigned long long o2[7];
            #pragma unroll
            for (int r = 0; r < 7; ++r) o2[r] = 0ull;
            const float* aB = attnS + hh * 2450;
            for (int m = 0; m < 49; ++m) {
                unsigned long long v2 = *(const unsigned long long*)
                    (qkvh + m * 194 + 128 + hh * 32 + 2 * dp);
                #pragma unroll
                for (int r = 0; r < 7; ++r) {
                    unsigned long long ap2 = pack2(aB[trow[r] * 50 + m]);
                    fma2(o2[r], ap2, v2);
                }
            }
            #pragma unroll
            for (int r = 0; r < 7; ++r) {
                if (tval[r]) {
                    float2 f = unpack2(o2[r]);
                    unsigned short hx, lx, hy, ly;
                    cvt_split(f.x, hx, lx);
                    cvt_split(f.y, hy, ly);
                    size_t o = (size_t)tokS[trow[r]] * 384
                               + (2 * hp + hh) * 32 + 2 * dp;
                    *(ushort2*)(ahi + o) = make_ushort2(hx, hy);
                    *(ushort2*)(alo + o) = make_ushort2(lx, ly);
                }
            }
        }
        __syncthreads();
    }
}

// ============================================================================
extern "C" void kernel_launch(void* const* d_in, const int* in_sizes, int n_in,
                              void* d_out, int out_size)
{
    const float* x     = (const float*)d_in[0];
    const float* qkvw  = (const float*)d_in[1];
    const float* qkvb  = (const float*)d_in[2];
    const float* projw = (const float*)d_in[3];
    const float* projb = (const float*)d_in[4];
    const float* table = (const float*)d_in[5];
    float* out = (float*)d_out;

    float *gq;
    unsigned short *xhi, *xlo, *ahi, *alo, *whi, *wlo, *phi, *plo;
    cudaGetSymbolAddress((void**)&gq,  g_qkv);
    cudaGetSymbolAddress((void**)&xhi, g_xhi);
    cudaGetSymbolAddress((void**)&xlo, g_xlo);
    cudaGetSymbolAddress((void**)&ahi, g_ahi);
    cudaGetSymbolAddress((void**)&alo, g_alo);
    cudaGetSymbolAddress((void**)&whi, g_whi);
    cudaGetSymbolAddress((void**)&wlo, g_wlo);
    cudaGetSymbolAddress((void**)&phi, g_phi);
    cudaGetSymbolAddress((void**)&plo, g_plo);

    cudaFuncSetAttribute(gemm_bf16x3_kernel,
                         cudaFuncAttributeMaxDynamicSharedMemorySize, GSMEM_BYTES);
    cudaFuncSetAttribute(swin_attn_kernel,
                         cudaFuncAttributeMaxDynamicSharedMemorySize,
                         K2_WORDS * (int)sizeof(float));

    // K0: splits
    split_bf16_kernel<<<18816, 256>>>((const float4*)x, (ushort4*)xhi,
                                      (ushort4*)xlo, 4816896);
    split_bf16_kernel<<<432, 256>>>((const float4*)qkvw, (ushort4*)whi,
                                    (ushort4*)wlo, 110592);
    split_bf16_kernel<<<144, 256>>>((const float4*)projw, (ushort4*)phi,
                                    (ushort4*)plo, 36864);

    // K1 / K2 / K3
    gemm_bf16x3_kernel<<<dim3(392, 9), 256, GSMEM_BYTES>>>(
        xhi, xlo, whi, wlo, qkvb, gq, 1152, 1);
    swin_attn_kernel<<<1024, 256, K2_WORDS * sizeof(float)>>>(gq, table, ahi, alo);
    gemm_bf16x3_kernel<<<dim3(392, 3), 256, GSMEM_BYTES>>>(
        ahi, alo, phi, plo, projb, out, 384, 0);
}

// round 8
// speedup vs baseline: 3.6134x; 1.0103x over previous
#include <cuda_runtime.h>
#include <cuda_bf16.h>
#include <cstdint>

// ============================================================================
// Shifted-window attention pipeline:
//   K0: split X / qkvw / projw into bf16 (hi, lo) pairs        (elementwise)
//   K1: g_qkv = X @ qkvw^T + qkvb    (mma.sync bf16 3-term, cp.async 2-stage)
//   K2: per-window attention via mma.sync (QK^T and A@V on tensor pipe)
//   K3: out = attno @ projw^T + projb (same GEMM, bf16 inputs direct)
// ============================================================================

#define KDIM 384
#define NTOKENS 50176   // 16*56*56 = 392*128

static __device__ float          g_qkv[(size_t)NTOKENS * 1152];
static __device__ unsigned short g_xhi[(size_t)NTOKENS * 384];
static __device__ unsigned short g_xlo[(size_t)NTOKENS * 384];
static __device__ unsigned short g_ahi[(size_t)NTOKENS * 384];
static __device__ unsigned short g_alo[(size_t)NTOKENS * 384];
static __device__ unsigned short g_whi[1152 * 384];
static __device__ unsigned short g_wlo[1152 * 384];
static __device__ unsigned short g_phi[384 * 384];
static __device__ unsigned short g_plo[384 * 384];

__device__ __forceinline__ uint32_t smem_u32(const void* p) {
    uint32_t a;
    asm("{ .reg .u64 t; cvta.to.shared.u64 t, %1; cvt.u32.u64 %0, t; }"
        : "=r"(a) : "l"(p));
    return a;
}
#define LDM4(r0, r1, r2, r3, addr)                                           \
    asm volatile("ldmatrix.sync.aligned.m8n8.x4.shared.b16 {%0,%1,%2,%3}, [%4];" \
                 : "=r"(r0), "=r"(r1), "=r"(r2), "=r"(r3) : "r"(addr))
#define LDM4T(r0, r1, r2, r3, addr)                                          \
    asm volatile("ldmatrix.sync.aligned.m8n8.x4.trans.shared.b16 {%0,%1,%2,%3}, [%4];" \
                 : "=r"(r0), "=r"(r1), "=r"(r2), "=r"(r3) : "r"(addr))
#define MMA_BF16(c, a, b)                                                    \
    asm volatile("mma.sync.aligned.m16n8k16.row.col.f32.bf16.bf16.f32 "      \
                 "{%0,%1,%2,%3}, {%4,%5,%6,%7}, {%8,%9}, {%0,%1,%2,%3};"     \
                 : "+f"((c)[0]), "+f"((c)[1]), "+f"((c)[2]), "+f"((c)[3])    \
                 : "r"((a)[0]), "r"((a)[1]), "r"((a)[2]), "r"((a)[3]),       \
                   "r"((b)[0]), "r"((b)[1]))
#define CPA16(dst, src)                                                      \
    asm volatile("cp.async.ca.shared.global [%0], [%1], 16;" :: "r"(dst), "l"(src))
#define CPA_COMMIT() asm volatile("cp.async.commit_group;")
#define CPA_WAIT1()  asm volatile("cp.async.wait_group 1;")
#define CPA_WAIT0()  asm volatile("cp.async.wait_group 0;")

__device__ __forceinline__ void cvt_split(float x, unsigned short& h,
                                          unsigned short& l) {
    __nv_bfloat16 bh = __float2bfloat16_rn(x);
    h = __bfloat16_as_ushort(bh);
    l = __bfloat16_as_ushort(__float2bfloat16_rn(x - __bfloat162float(bh)));
}

// ============================================================================
// K0: fp32 -> bf16 hi/lo split
// ============================================================================
__global__ void __launch_bounds__(256)
split_bf16_kernel(const float4* __restrict__ in, ushort4* __restrict__ hi,
                  ushort4* __restrict__ lo, int n4)
{
    int i = blockIdx.x * 256 + threadIdx.x;
    if (i >= n4) return;
    float4 v = in[i];
    ushort4 h, l;
    cvt_split(v.x, h.x, l.x);
    cvt_split(v.y, h.y, l.y);
    cvt_split(v.z, h.z, l.z);
    cvt_split(v.w, h.w, l.w);
    hi[i] = h;
    lo[i] = l;
}

// ============================================================================
// K1/K3 GEMM (unchanged from R7, proven)
// ============================================================================
#define GSTR 72
#define TILE_US (128 * GSTR)
#define STAGE_US (4 * TILE_US)
#define GSMEM_BYTES (2 * STAGE_US * 2)

__global__ void __launch_bounds__(256, 1)
gemm_bf16x3_kernel(const unsigned short* __restrict__ Ahi_g,
                   const unsigned short* __restrict__ Alo_g,
                   const unsigned short* __restrict__ Bhi_g,
                   const unsigned short* __restrict__ Blo_g,
                   const float* __restrict__ bias, float* __restrict__ C,
                   int ncols, int qflag)
{
    extern __shared__ __align__(16) unsigned short gsm[];

    const int tid  = threadIdx.x;
    const int lane = tid & 31;
    const int wid  = tid >> 5;
    const int wm   = wid & 3;
    const int wn   = wid >> 2;
    const int mbase = blockIdx.x * 128;
    const int nbase = blockIdx.y * 128;
    const uint32_t sbase = smem_u32(gsm);

    const int lr = lane & 7, lq = lane >> 3;
    const uint32_t aoff =
        (uint32_t)((((lq & 1) * 8 + lr) * GSTR + (lq >> 1) * 8) * 2);
    const uint32_t boff =
        (uint32_t)((((lq >> 1) * 8 + lr) * GSTR + (lq & 1) * 8) * 2);

    float c[2][8][4];
    #pragma unroll
    for (int mt = 0; mt < 2; ++mt)
        #pragma unroll
        for (int nt = 0; nt < 8; ++nt)
            #pragma unroll
            for (int i = 0; i < 4; ++i) c[mt][nt][i] = 0.f;

    auto prefetch = [&](int sbuf, int kc) {
        const uint32_t st = sbase + (uint32_t)sbuf * (STAGE_US * 2);
        #pragma unroll
        for (int j = 0; j < 4; ++j) {
            int cch = tid + 256 * j;
            int row = cch >> 3, c8 = cch & 7;
            uint32_t doff = (uint32_t)(row * 144 + c8 * 16);
            size_t aidx = (size_t)(mbase + row) * KDIM + kc * 64 + c8 * 8;
            size_t bidx = (size_t)(nbase + row) * KDIM + kc * 64 + c8 * 8;
            CPA16(st + doff, Ahi_g + aidx);
            CPA16(st + TILE_US * 2 + doff, Alo_g + aidx);
            CPA16(st + TILE_US * 4 + doff, Bhi_g + bidx);
            CPA16(st + TILE_US * 6 + doff, Blo_g + bidx);
        }
        CPA_COMMIT();
    };

    prefetch(0, 0);

    for (int kc = 0; kc < 6; ++kc) {
        if (kc + 1 < 6) {
            prefetch((kc + 1) & 1, kc + 1);
            CPA_WAIT1();
        } else {
            CPA_WAIT0();
        }
        __syncthreads();

        const uint32_t st = sbase + (uint32_t)(kc & 1) * (STAGE_US * 2);
        const uint32_t sAhi = st;
        const uint32_t sAlo = st + TILE_US * 2;
        const uint32_t sBhi = st + TILE_US * 4;
        const uint32_t sBlo = st + TILE_US * 6;

        #pragma unroll
        for (int ks = 0; ks < 4; ++ks) {
            const uint32_t kb = (uint32_t)(ks * 32);
            uint32_t ah[2][4], al[2][4];
            #pragma unroll
            for (int mt = 0; mt < 2; ++mt) {
                uint32_t base = (uint32_t)((wm * 32 + mt * 16) * (GSTR * 2)) + kb;
                LDM4(ah[mt][0], ah[mt][1], ah[mt][2], ah[mt][3], sAhi + base + aoff);
                LDM4(al[mt][0], al[mt][1], al[mt][2], al[mt][3], sAlo + base + aoff);
            }
            uint32_t bh[8][2], bl[8][2];
            #pragma unroll
            for (int ntp = 0; ntp < 4; ++ntp) {
                uint32_t base = (uint32_t)((wn * 64 + ntp * 16) * (GSTR * 2)) + kb;
                LDM4(bh[2*ntp][0], bh[2*ntp][1], bh[2*ntp+1][0], bh[2*ntp+1][1],
                     sBhi + base + boff);
                LDM4(bl[2*ntp][0], bl[2*ntp][1], bl[2*ntp+1][0], bl[2*ntp+1][1],
                     sBlo + base + boff);
            }
            #pragma unroll
            for (int mt = 0; mt < 2; ++mt)
                #pragma unroll
                for (int nt = 0; nt < 8; ++nt) {
                    MMA_BF16(c[mt][nt], ah[mt], bh[nt]);
                    MMA_BF16(c[mt][nt], ah[mt], bl[nt]);
                    MMA_BF16(c[mt][nt], al[mt], bh[nt]);
                }
        }
        __syncthreads();
    }

    const float qscale = 0.17677669529663687f;
    #pragma unroll
    for (int mt = 0; mt < 2; ++mt) {
        #pragma unroll
        for (int nt = 0; nt < 8; ++nt) {
            int row0 = mbase + wm * 32 + mt * 16 + (lane >> 2);
            int col  = nbase + wn * 64 + nt * 8 + (lane & 3) * 2;
            float sc = (qflag && col < 384) ? qscale : 1.0f;
            float b0 = __ldg(bias + col), b1 = __ldg(bias + col + 1);
            float2 v0 = make_float2((c[mt][nt][0] + b0) * sc,
                                    (c[mt][nt][1] + b1) * sc);
            float2 v1 = make_float2((c[mt][nt][2] + b0) * sc,
                                    (c[mt][nt][3] + b1) * sc);
            *(float2*)(C + (size_t)row0 * ncols + col) = v0;
            *(float2*)(C + (size_t)(row0 + 8) * ncols + col) = v1;
        }
    }
}

// ============================================================================
// K2: per-window attention with mma.sync.
// Smem (ushort units, stride 72):
//   Qh|Ql|Kh|Kl|Vh|Vl : 6 x [64][72]  head-pair tiles (d = 64)
//   Ph|Pl             : 2 x [64][72]  probs (k = token), pad stays zero
// Floats after: attnS [64][58], biasP[338], ints 4x49.
// ============================================================================
#define T2_US 4608            // 64*72
#define K2_QH 0
#define K2_QL (1*T2_US)
#define K2_KH (2*T2_US)
#define K2_KL (3*T2_US)
#define K2_VH (4*T2_US)
#define K2_VL (5*T2_US)
#define K2_PH (6*T2_US)
#define K2_PL (7*T2_US)
#define K2_ATT_F 18432        // float index (= 8*T2_US ushorts / 2)
#define K2_BIAS_F (K2_ATT_F + 3712)
#define K2_INTS_F (K2_BIAS_F + 338)
#define K2_TOTAL_F (K2_INTS_F + 196)   // 22678 floats = 90712 B
#define K2_SMEM_BYTES 90752

__global__ void __launch_bounds__(256, 2)
swin_attn_mma_kernel(const float* __restrict__ qkv,
                     const float* __restrict__ table,
                     unsigned short* __restrict__ ahi,
                     unsigned short* __restrict__ alo)
{
    extern __shared__ float sf[];
    unsigned short* su = (unsigned short*)sf;
    float* attnS = sf + K2_ATT_F;          // [64][58]
    float* biasP = sf + K2_BIAS_F;         // [2][169]
    int*   tokS  = (int*)(sf + K2_INTS_F);
    int*   regS  = tokS + 49;
    int*   rowS  = regS + 49;
    int*   colS  = rowS + 49;

    const int tid  = threadIdx.x;
    const int lane = tid & 31;
    const int wid  = tid >> 5;
    const int mt   = wid & 3;       // m-tile (16 out rows)
    const int nh   = wid >> 2;      // n-half / d-half
    const int w    = blockIdx.x;
    const int b    = w >> 6;
    const int wi   = w & 63;
    const int wr   = wi >> 3;
    const int wc   = wi & 7;

    const uint32_t sb = smem_u32(su);
    const int lr = lane & 7, lq = lane >> 3;
    const uint32_t aoff =
        (uint32_t)((((lq & 1) * 8 + lr) * 72 + (lq >> 1) * 8) * 2);
    const uint32_t boff =
        (uint32_t)((((lq >> 1) * 8 + lr) * 72 + (lq & 1) * 8) * 2);

    // zero all 8 tiles once (pad rows/cols stay zero forever)
    {
        unsigned long long* z = (unsigned long long*)su;
        for (int i = tid; i < 8 * T2_US / 4; i += 256) z[i] = 0ull;
    }

    if (tid < 49) {
        int tr = tid / 7, tc = tid - tr * 7;
        rowS[tid] = tr; colS[tid] = tc;
        int gr = wr * 7 + tr, gc = wc * 7 + tc;
        int rh = (gr < 49) ? 0 : (gr < 53 ? 1 : 2);
        int rw = (gc < 49) ? 0 : (gc < 53 ? 1 : 2);
        regS[tid] = rh * 3 + rw;
        int sr = gr + 3; if (sr >= 56) sr -= 56;
        int sc = gc + 3; if (sc >= 56) sc -= 56;
        tokS[tid] = (b * 56 + sr) * 56 + sc;
    }
    __syncthreads();

    for (int hp = 0; hp < 6; ++hp) {
        // ---- stage bias pair + QKV pair tiles (bf16 hi/lo) ----
        for (int i = tid; i < 338; i += 256) {
            int hh = (i >= 169) ? 1 : 0;
            biasP[i] = table[(i - 169 * hh) * 12 + 2 * hp + hh];
        }
        for (int i = tid; i < 49 * 96; i += 256) {
            int t = i / 96, f2 = i - t * 96;
            int s = f2 >> 5, d2 = f2 & 31;      // s: 0=q 1=k 2=v; d pair
            float2 v = *(const float2*)
                (qkv + (size_t)tokS[t] * 1152 + s * 384 + hp * 64 + 2 * d2);
            unsigned short hx, lx, hy, ly;
            cvt_split(v.x, hx, lx);
            cvt_split(v.y, hy, ly);
            int o = t * 72 + 2 * d2;
            *(ushort2*)(su + s * 2 * T2_US + o)         = make_ushort2(hx, hy);
            *(ushort2*)(su + (s * 2 + 1) * T2_US + o)   = make_ushort2(lx, ly);
        }
        __syncthreads();

        for (int h = 0; h < 2; ++h) {
            // ================= QK^T (warp: m-tile mt, n-tiles nh*4..+3) ======
            {
                uint32_t qh[2][4], ql[2][4];
                #pragma unroll
                for (int ks = 0; ks < 2; ++ks) {
                    uint32_t base = (uint32_t)((mt * 16) * 144
                                    + (h * 32 + ks * 16) * 2);
                    LDM4(qh[ks][0], qh[ks][1], qh[ks][2], qh[ks][3],
                         sb + K2_QH * 2 + base + aoff);
                    LDM4(ql[ks][0], ql[ks][1], ql[ks][2], ql[ks][3],
                         sb + K2_QL * 2 + base + aoff);
                }
                float c[4][4];
                #pragma unroll
                for (int nt = 0; nt < 4; ++nt)
                    #pragma unroll
                    for (int i = 0; i < 4; ++i) c[nt][i] = 0.f;

                #pragma unroll
                for (int ks = 0; ks < 2; ++ks) {
                    uint32_t kh[4][2], kl[4][2];
                    #pragma unroll
                    for (int lp = 0; lp < 2; ++lp) {
                        int ntp = nh * 2 + lp;
                        uint32_t base = (uint32_t)((ntp * 16) * 144
                                        + (h * 32 + ks * 16) * 2);
                        LDM4(kh[2*lp][0], kh[2*lp][1], kh[2*lp+1][0], kh[2*lp+1][1],
                             sb + K2_KH * 2 + base + boff);
                        LDM4(kl[2*lp][0], kl[2*lp][1], kl[2*lp+1][0], kl[2*lp+1][1],
                             sb + K2_KL * 2 + base + boff);
                    }
                    #pragma unroll
                    for (int nt = 0; nt < 4; ++nt) {
                        MMA_BF16(c[nt], qh[ks], kh[nt]);
                        MMA_BF16(c[nt], qh[ks], kl[nt]);
                        MMA_BF16(c[nt], ql[ks], kh[nt]);
                    }
                }
                // store logits (skip global n-tile 7 = pure pad)
                #pragma unroll
                for (int nt = 0; nt < 4; ++nt) {
                    int gnt = nh * 4 + nt;
                    if (gnt == 7) continue;
                    int row = mt * 16 + (lane >> 2);
                    int col = gnt * 8 + (lane & 3) * 2;
                    *(float2*)(attnS + row * 58 + col) =
                        make_float2(c[nt][0], c[nt][1]);
                    *(float2*)(attnS + (row + 8) * 58 + col) =
                        make_float2(c[nt][2], c[nt][3]);
                }
            }
            __syncthreads();

            // ================= softmax + bias + mask -> P hi/lo ==============
            for (int row = wid; row < 49; row += 8) {
                const float* ap = attnS + row * 58;
                int ri = rowS[row], ci = colS[row], rg = regS[row];
                float v0, v1;
                {
                    int j = lane;
                    if (j < 49) {
                        int rel = (ri - rowS[j] + 6) * 13 + (ci - colS[j] + 6);
                        v0 = ap[j] + biasP[h * 169 + rel];
                        if (rg != regS[j]) v0 -= 100.0f;
                    } else v0 = -3.0e38f;
                }
                {
                    int j = 32 + lane;
                    if (j < 49) {
                        int rel = (ri - rowS[j] + 6) * 13 + (ci - colS[j] + 6);
                        v1 = ap[j] + biasP[h * 169 + rel];
                        if (rg != regS[j]) v1 -= 100.0f;
                    } else v1 = -3.0e38f;
                }
                float m = fmaxf(v0, v1);
                #pragma unroll
                for (int off = 16; off; off >>= 1)
                    m = fmaxf(m, __shfl_xor_sync(0xffffffffu, m, off));
                float e0 = (lane < 49) ? __expf(v0 - m) : 0.f;
                float e1 = (32 + lane < 49) ? __expf(v1 - m) : 0.f;
                float s = e0 + e1;
                #pragma unroll
                for (int off = 16; off; off >>= 1)
                    s += __shfl_xor_sync(0xffffffffu, s, off);
                float inv = 1.0f / s;
                unsigned short ph, pl;
                cvt_split(e0 * inv, ph, pl);
                su[K2_PH + row * 72 + lane] = ph;
                su[K2_PL + row * 72 + lane] = pl;
                if (32 + lane < 49) {
                    cvt_split(e1 * inv, ph, pl);
                    su[K2_PH + row * 72 + 32 + lane] = ph;
                    su[K2_PL + row * 72 + 32 + lane] = pl;
                }
            }
            __syncthreads();

            // ================= out = P @ V (warp: mt, d-tiles nh*2..+1) ======
            {
                float c2[2][4];
                #pragma unroll
                for (int dt = 0; dt < 2; ++dt)
                    #pragma unroll
                    for (int i = 0; i < 4; ++i) c2[dt][i] = 0.f;

                // V ldmatrix.trans per-lane byte offset (within k-step/d-half)
                const uint32_t vlo =
                    (uint32_t)((((lq & 1) * 8 + lr) * 144)
                               + ((h * 32 + nh * 16 + (lq >> 1) * 8) * 2));

                #pragma unroll
                for (int ks = 0; ks < 4; ++ks) {
                    uint32_t aPh[4], aPl[4];
                    uint32_t base = (uint32_t)((mt * 16) * 144 + ks * 32);
                    LDM4(aPh[0], aPh[1], aPh[2], aPh[3],
                         sb + K2_PH * 2 + base + aoff);
                    LDM4(aPl[0], aPl[1], aPl[2], aPl[3],
                         sb + K2_PL * 2 + base + aoff);

                    uint32_t vh[2][2], vl[2][2];
                    uint32_t vbase = (uint32_t)((16 * ks) * 144);
                    LDM4T(vh[0][0], vh[0][1], vh[1][0], vh[1][1],
                          sb + K2_VH * 2 + vbase + vlo);
                    LDM4T(vl[0][0], vl[0][1], vl[1][0], vl[1][1],
                          sb + K2_VL * 2 + vbase + vlo);

                    #pragma unroll
                    for (int dt = 0; dt < 2; ++dt) {
                        MMA_BF16(c2[dt], aPh, vh[dt]);
                        MMA_BF16(c2[dt], aPh, vl[dt]);
                        MMA_BF16(c2[dt], aPl, vh[dt]);
                    }
                }
                // write bf16 hi/lo output (rows < 49 only)
                #pragma unroll
                for (int dt = 0; dt < 2; ++dt) {
                    int r0 = mt * 16 + (lane >> 2);
                    int col = (2 * hp + h) * 32 + (nh * 2 + dt) * 8
                              + (lane & 3) * 2;
                    if (r0 < 49) {
                        unsigned short hx, lx, hy, ly;
                        cvt_split(c2[dt][0], hx, lx);
                        cvt_split(c2[dt][1], hy, ly);
                        size_t o = (size_t)tokS[r0] * 384 + col;
                        *(ushort2*)(ahi + o) = make_ushort2(hx, hy);
                        *(ushort2*)(alo + o) = make_ushort2(lx, ly);
                    }
                    int r1 = r0 + 8;
                    if (r1 < 49) {
                        unsigned short hx, lx, hy, ly;
                        cvt_split(c2[dt][2], hx, lx);
                        cvt_split(c2[dt][3], hy, ly);
                        size_t o = (size_t)tokS[r1] * 384 + col;
                        *(ushort2*)(ahi + o) = make_ushort2(hx, hy);
                        *(ushort2*)(alo + o) = make_ushort2(lx, ly);
                    }
                }
            }
            __syncthreads();
        }
    }
}

// ============================================================================
extern "C" void kernel_launch(void* const* d_in, const int* in_sizes, int n_in,
                              void* d_out, int out_size)
{
    const float* x     = (const float*)d_in[0];
    const float* qkvw  = (const float*)d_in[1];
    const float* qkvb  = (const float*)d_in[2];
    const float* projw = (const float*)d_in[3];
    const float* projb = (const float*)d_in[4];
    const float* table = (const float*)d_in[5];
    float* out = (float*)d_out;

    float *gq;
    unsigned short *xhi, *xlo, *ahi, *alo, *whi, *wlo, *phi, *plo;
    cudaGetSymbolAddress((void**)&gq,  g_qkv);
    cudaGetSymbolAddress((void**)&xhi, g_xhi);
    cudaGetSymbolAddress((void**)&xlo, g_xlo);
    cudaGetSymbolAddress((void**)&ahi, g_ahi);
    cudaGetSymbolAddress((void**)&alo, g_alo);
    cudaGetSymbolAddress((void**)&whi, g_whi);
    cudaGetSymbolAddress((void**)&wlo, g_wlo);
    cudaGetSymbolAddress((void**)&phi, g_phi);
    cudaGetSymbolAddress((void**)&plo, g_plo);

    cudaFuncSetAttribute(gemm_bf16x3_kernel,
                         cudaFuncAttributeMaxDynamicSharedMemorySize, GSMEM_BYTES);
    cudaFuncSetAttribute(swin_attn_mma_kernel,
                         cudaFuncAttributeMaxDynamicSharedMemorySize, K2_SMEM_BYTES);

    split_bf16_kernel<<<18816, 256>>>((const float4*)x, (ushort4*)xhi,
                                      (ushort4*)xlo, 4816896);
    split_bf16_kernel<<<432, 256>>>((const float4*)qkvw, (ushort4*)whi,
                                    (ushort4*)wlo, 110592);
    split_bf16_kernel<<<144, 256>>>((const float4*)projw, (ushort4*)phi,
                                    (ushort4*)plo, 36864);

    gemm_bf16x3_kernel<<<dim3(392, 9), 256, GSMEM_BYTES>>>(
        xhi, xlo, whi, wlo, qkvb, gq, 1152, 1);
    swin_attn_mma_kernel<<<1024, 256, K2_SMEM_BYTES>>>(gq, table, ahi, alo);
    gemm_bf16x3_kernel<<<dim3(392, 3), 256, GSMEM_BYTES>>>(
        ahi, alo, phi, plo, projb, out, 384, 0);
}